// round 1
// baseline (speedup 1.0000x reference)
#include <cuda_runtime.h>

#define N0_   260000
#define N1_   10240
#define B_    1024
#define E0_   256000
#define E1_   10240
#define IN_C  602
#define HID   256
#define OUT_C 41

// Scratch (allocation-free rule: __device__ globals)
__device__ float g_agg0[N1_ * IN_C];   // layer-0 mean aggregation  [10240, 602]
__device__ float g_h[N1_ * HID];       // layer-0 output (post-relu) [10240, 256]
__device__ float g_agg1[B_ * HID];     // layer-1 mean aggregation  [1024, 256]

__device__ __forceinline__ int lower_bound_i(const int* __restrict__ a, int n, int v) {
    int lo = 0, hi = n;
    while (lo < hi) {
        int mid = (lo + hi) >> 1;
        if (a[mid] < v) lo = mid + 1; else hi = mid;
    }
    return lo;
}

// ---------------------------------------------------------------------------
// Kernel A: layer-0 segment mean. One CTA per target node (dst0 is sorted).
// 256 threads; thread t owns columns t, t+256, t+512.
// ---------------------------------------------------------------------------
__global__ void agg0_kernel(const float* __restrict__ x,
                            const int* __restrict__ src,
                            const int* __restrict__ dst) {
    const int t = blockIdx.x;
    const int start = lower_bound_i(dst, E0_, t);
    const int end   = lower_bound_i(dst, E0_, t + 1);

    const int tid = threadIdx.x;
    const int c0 = tid, c1 = tid + 256, c2 = tid + 512;

    float a0 = 0.f, a1 = 0.f, a2 = 0.f;
    for (int e = start; e < end; ++e) {
        const float* row = x + (long long)src[e] * IN_C;
        a0 += row[c0];
        a1 += row[c1];
        if (c2 < IN_C) a2 += row[c2];
    }
    const float inv = 1.0f / (float)max(end - start, 1);
    float* o = g_agg0 + (long long)t * IN_C;
    o[c0] = a0 * inv;
    o[c1] = a1 * inv;
    if (c2 < IN_C) o[c2] = a2 * inv;
}

// ---------------------------------------------------------------------------
// Kernel B: h = relu(b_l0 + agg0 @ W_l0 + x[:N1] @ W_r0)
// M=10240, N=256, K=602 (x2 passes). BM=128, BN=64, BK=8, 8x4 per thread.
// ---------------------------------------------------------------------------
__global__ __launch_bounds__(256)
void gemm0_kernel(const float* __restrict__ x,
                  const float* __restrict__ W_l,
                  const float* __restrict__ W_r,
                  const float* __restrict__ bias) {
    constexpr int BM = 128, BN = 64, BK = 8;
    __shared__ float As[BK][BM];
    __shared__ float Bs[BK][BN];

    const int tid  = threadIdx.x;
    const int row0 = blockIdx.y * BM;
    const int col0 = blockIdx.x * BN;
    const int tx = tid & 15;   // 16 column groups of 4
    const int ty = tid >> 4;   // 16 row groups of 8

    float acc[8][4];
    #pragma unroll
    for (int i = 0; i < 8; ++i)
        #pragma unroll
        for (int j = 0; j < 4; ++j) acc[i][j] = 0.f;

    // A-tile load mapping: each thread loads 4 consecutive-k elements
    const int lm  = tid >> 1;          // 0..127
    const int lk4 = (tid & 1) * 4;     // 0 or 4
    // B-tile load mapping: 2 elements per thread
    const int ln  = tid & 63;
    const int lkk = tid >> 6;          // 0..3 (and +4)

    #pragma unroll 1
    for (int pass = 0; pass < 2; ++pass) {
        const float* A = pass ? x   : g_agg0;
        const float* W = pass ? W_r : W_l;

        for (int k0 = 0; k0 < IN_C; k0 += BK) {
            // load A tile (transposed into smem)
            {
                const float* ap = A + (long long)(row0 + lm) * IN_C + k0 + lk4;
                #pragma unroll
                for (int i = 0; i < 4; ++i) {
                    int k = k0 + lk4 + i;
                    As[lk4 + i][lm] = (k < IN_C) ? ap[i] : 0.f;
                }
            }
            // load B tile
            {
                #pragma unroll
                for (int i = 0; i < 2; ++i) {
                    int kk = lkk + i * 4;
                    int k  = k0 + kk;
                    Bs[kk][ln] = (k < IN_C) ? W[(long long)k * HID + col0 + ln] : 0.f;
                }
            }
            __syncthreads();

            #pragma unroll
            for (int kk = 0; kk < BK; ++kk) {
                float4 av0 = *reinterpret_cast<const float4*>(&As[kk][ty * 8]);
                float4 av1 = *reinterpret_cast<const float4*>(&As[kk][ty * 8 + 4]);
                float4 bv  = *reinterpret_cast<const float4*>(&Bs[kk][tx * 4]);
                float a[8] = {av0.x, av0.y, av0.z, av0.w, av1.x, av1.y, av1.z, av1.w};
                float b[4] = {bv.x, bv.y, bv.z, bv.w};
                #pragma unroll
                for (int i = 0; i < 8; ++i)
                    #pragma unroll
                    for (int j = 0; j < 4; ++j)
                        acc[i][j] += a[i] * b[j];
            }
            __syncthreads();
        }
    }

    // epilogue: + bias, relu, store
    #pragma unroll
    for (int i = 0; i < 8; ++i) {
        const int r = row0 + ty * 8 + i;
        #pragma unroll
        for (int j = 0; j < 4; ++j) {
            const int c = col0 + tx * 4 + j;
            float v = acc[i][j] + bias[c];
            g_h[(long long)r * HID + c] = fmaxf(v, 0.f);
        }
    }
}

// ---------------------------------------------------------------------------
// Kernel C: layer-1 segment mean over h. One CTA per batch target; 256 threads
// (one per hidden channel).
// ---------------------------------------------------------------------------
__global__ void agg1_kernel(const int* __restrict__ src,
                            const int* __restrict__ dst) {
    const int t = blockIdx.x;
    const int start = lower_bound_i(dst, E1_, t);
    const int end   = lower_bound_i(dst, E1_, t + 1);
    const int tid = threadIdx.x;

    float acc = 0.f;
    for (int e = start; e < end; ++e)
        acc += g_h[src[e] * HID + tid];

    g_agg1[t * HID + tid] = acc / (float)max(end - start, 1);
}

// ---------------------------------------------------------------------------
// Kernel D: out = log_softmax(b_l1 + agg1 @ W_l1 + h[:B] @ W_r1)
// One CTA (64 threads) per batch row; thread j<41 computes one logit.
// ---------------------------------------------------------------------------
__global__ void out_kernel(const float* __restrict__ W_l,
                           const float* __restrict__ bias,
                           const float* __restrict__ W_r,
                           float* __restrict__ out) {
    __shared__ float sA[HID];
    __shared__ float sH[HID];
    __shared__ float red[64];

    const int b = blockIdx.x;
    const int tid = threadIdx.x;

    for (int k = tid; k < HID; k += 64) {
        sA[k] = g_agg1[b * HID + k];
        sH[k] = g_h[b * HID + k];
    }
    __syncthreads();

    float v = -1e30f;
    if (tid < OUT_C) {
        float s = bias[tid];
        #pragma unroll 4
        for (int k = 0; k < HID; ++k)
            s += sA[k] * W_l[k * OUT_C + tid] + sH[k] * W_r[k * OUT_C + tid];
        v = s;
    }

    // max reduction over 64 lanes
    red[tid] = v;
    __syncthreads();
    #pragma unroll
    for (int off = 32; off > 0; off >>= 1) {
        if (tid < off) red[tid] = fmaxf(red[tid], red[tid + off]);
        __syncthreads();
    }
    const float m = red[0];
    __syncthreads();

    red[tid] = (tid < OUT_C) ? expf(v - m) : 0.f;
    __syncthreads();
    #pragma unroll
    for (int off = 32; off > 0; off >>= 1) {
        if (tid < off) red[tid] += red[tid + off];
        __syncthreads();
    }
    const float lse = logf(red[0]);

    if (tid < OUT_C)
        out[b * OUT_C + tid] = v - m - lse;
}

// ---------------------------------------------------------------------------
extern "C" void kernel_launch(void* const* d_in, const int* in_sizes, int n_in,
                              void* d_out, int out_size) {
    const float* x    = (const float*)d_in[0];
    const float* W_l0 = (const float*)d_in[1];
    const float* b_l0 = (const float*)d_in[2];
    const float* W_r0 = (const float*)d_in[3];
    const float* W_l1 = (const float*)d_in[4];
    const float* b_l1 = (const float*)d_in[5];
    const float* W_r1 = (const float*)d_in[6];
    const int* src0   = (const int*)d_in[7];
    const int* dst0   = (const int*)d_in[8];
    const int* src1   = (const int*)d_in[9];
    const int* dst1   = (const int*)d_in[10];
    float* out = (float*)d_out;

    agg0_kernel<<<N1_, 256>>>(x, src0, dst0);
    gemm0_kernel<<<dim3(HID / 64, N1_ / 128), 256>>>(x, W_l0, W_r0, b_l0);
    agg1_kernel<<<B_, 256>>>(src1, dst1);
    out_kernel<<<B_, 64>>>(W_l1, b_l1, W_r1, out);
}

// round 4
// speedup vs baseline: 1.4782x; 1.4782x over previous
#include <cuda_runtime.h>
#include <cuda_bf16.h>
#include <cstdint>

#define N0_   260000
#define N1_   10240
#define B_    1024
#define E0_   256000
#define E1_   10240
#define IN_C  602
#define HID   256
#define OUT_C 41
#define KHALF 640
#define KTOT  1280          // [agg (640) | x (640)] combined K
#define NCHUNK 20           // K chunks of 64

// ---------------- scratch (__device__ globals) ------------------------------
__device__ __nv_bfloat16 g_ah[(size_t)N1_ * KTOT];   // A hi  [10240][1280]
__device__ __nv_bfloat16 g_al[(size_t)N1_ * KTOT];   // A lo
__device__ __nv_bfloat16 g_wh[(size_t)HID * KTOT];   // W^T hi [256][1280]
__device__ __nv_bfloat16 g_wl[(size_t)HID * KTOT];   // W^T lo
__device__ float g_h[(size_t)N1_ * HID];             // layer-0 output
__device__ float g_w1t[2 * OUT_C * HID];             // layer-1 weights transposed

// ---------------- PTX macros (portable sm_80+ forms only) -------------------
#define CP_ASYNC16(dst, src) \
    asm volatile("cp.async.cg.shared.global [%0], [%1], 16;" \
        :: "r"((uint32_t)(dst)), "l"(src) : "memory")

#define CP_COMMIT() asm volatile("cp.async.commit_group;" ::: "memory")
#define CP_WAIT1()  asm volatile("cp.async.wait_group 1;" ::: "memory")

#define LDMATRIX_X4(r0, r1, r2, r3, addr) \
    asm volatile("ldmatrix.sync.aligned.m8n8.x4.shared.b16 {%0,%1,%2,%3}, [%4];" \
        : "=r"(r0), "=r"(r1), "=r"(r2), "=r"(r3) : "r"((uint32_t)(addr)))

#define MMA_BF16(d, a, b0_, b1_) \
    asm volatile("mma.sync.aligned.m16n8k16.row.col.f32.bf16.bf16.f32 " \
        "{%0,%1,%2,%3}, {%4,%5,%6,%7}, {%8,%9}, {%0,%1,%2,%3};" \
        : "+f"((d)[0]), "+f"((d)[1]), "+f"((d)[2]), "+f"((d)[3]) \
        : "r"((a)[0]), "r"((a)[1]), "r"((a)[2]), "r"((a)[3]), \
          "r"(b0_), "r"(b1_))

#define SWZ128(o) ((o) ^ (((o) >> 3) & 0x70))

// ---------------------------------------------------------------------------
__device__ __forceinline__ int lower_bound_i(const int* __restrict__ a, int n, int v) {
    int lo = 0;
    int hi = n;
    while (lo < hi) {
        int mid = (lo + hi) >> 1;
        if (a[mid] < v) lo = mid + 1; else hi = mid;
    }
    return lo;
}

__device__ __forceinline__ void store_hl(__nv_bfloat16* H, __nv_bfloat16* L,
                                         size_t idx, float v) {
    __nv_bfloat16 h = __float2bfloat16(v);
    H[idx] = h;
    L[idx] = __float2bfloat16(v - __bfloat162float(h));
}

// ---------------------------------------------------------------------------
// prep: x[:N1] -> A hi/lo columns [640..1279]
// ---------------------------------------------------------------------------
__global__ void conv_x_kernel(const float* __restrict__ x) {
    size_t i = (size_t)blockIdx.x * blockDim.x + threadIdx.x;
    if (i >= (size_t)N1_ * KHALF) return;
    int r = (int)(i / KHALF);
    int c = (int)(i % KHALF);
    float v = (c < IN_C) ? x[(size_t)r * IN_C + c] : 0.0f;
    store_hl(g_ah, g_al, (size_t)r * KTOT + KHALF + c, v);
}

// prep: W_l0 / W_r0 -> transposed combined hi/lo [n][ 0..639 | 640..1279 ]
__global__ void conv_w0_kernel(const float* __restrict__ Wl,
                               const float* __restrict__ Wr) {
    int i = blockIdx.x * blockDim.x + threadIdx.x;
    if (i >= 2 * HID * KHALF) return;
    int m = i / (HID * KHALF);
    int rem = i % (HID * KHALF);
    int n = rem / KHALF;
    int k = rem % KHALF;
    const float* W = m ? Wr : Wl;
    float v = (k < IN_C) ? W[(size_t)k * HID + n] : 0.0f;
    store_hl(g_wh, g_wl, (size_t)n * KTOT + (size_t)m * KHALF + k, v);
}

__global__ void conv_w1_kernel(const float* __restrict__ Wl,
                               const float* __restrict__ Wr) {
    int i = blockIdx.x * blockDim.x + threadIdx.x;
    if (i >= 2 * OUT_C * HID) return;
    int m = i / (OUT_C * HID);
    int rem = i % (OUT_C * HID);
    int c = rem / HID;
    int k = rem % HID;
    const float* W = m ? Wr : Wl;
    g_w1t[i] = W[(size_t)k * OUT_C + c];
}

// ---------------------------------------------------------------------------
// layer-0 segment mean (dst0 sorted): one CTA per target; writes A cols 0..639
// ---------------------------------------------------------------------------
__global__ __launch_bounds__(256)
void agg0_kernel(const float* __restrict__ x,
                 const int* __restrict__ src,
                 const int* __restrict__ dst) {
    const int t = blockIdx.x;
    const int start = lower_bound_i(dst, E0_, t);
    const int end   = lower_bound_i(dst, E0_, t + 1);
    const int tid = threadIdx.x;
    const int c0 = tid;
    const int c1 = tid + 256;
    const int c2 = tid + 512;

    float a0 = 0.0f, a1 = 0.0f, a2 = 0.0f;
    float b0 = 0.0f, b1 = 0.0f, b2 = 0.0f;
    int e = start;
    for (; e + 1 < end; e += 2) {
        const float* r0 = x + (size_t)src[e] * IN_C;
        const float* r1 = x + (size_t)src[e + 1] * IN_C;
        a0 += r0[c0]; b0 += r1[c0];
        a1 += r0[c1]; b1 += r1[c1];
        if (c2 < IN_C) { a2 += r0[c2]; b2 += r1[c2]; }
    }
    if (e < end) {
        const float* r0 = x + (size_t)src[e] * IN_C;
        a0 += r0[c0];
        a1 += r0[c1];
        if (c2 < IN_C) a2 += r0[c2];
    }
    const float inv = 1.0f / (float)max(end - start, 1);
    const size_t base = (size_t)t * KTOT;
    store_hl(g_ah, g_al, base + c0, (a0 + b0) * inv);
    store_hl(g_ah, g_al, base + c1, (a1 + b1) * inv);
    if (c2 < IN_C) {
        store_hl(g_ah, g_al, base + c2, (a2 + b2) * inv);
    } else if (c2 < KHALF) {
        store_hl(g_ah, g_al, base + c2, 0.0f);
    }
}

// ---------------------------------------------------------------------------
// layer-0 GEMM: h = relu(bias + A @ W^T) via mma.sync bf16 hi/lo split.
// CTA tile 128x128 (grid 80x2 = 160), warp tile 64x32, K chunks of 64,
// cp.async 2-stage pipeline, SW128 swizzled smem, ldmatrix operands.
// ---------------------------------------------------------------------------
#define STAGE_B  65536
#define OFF_AH   0
#define OFF_AL   16384
#define OFF_BH   32768
#define OFF_BL   49152
#define GSM_TOTAL (2 * STAGE_B)

__device__ __forceinline__ void load_stage(uint32_t sb, int kc, int m0, int n0, int tid) {
    #pragma unroll
    for (int j = 0; j < 4; ++j) {
        int i = tid + 256 * j;
        int row = i >> 3;
        int q = i & 7;
        uint32_t soff = SWZ128((uint32_t)(row * 128 + q * 16));
        const __nv_bfloat16* pah = g_ah + (size_t)(m0 + row) * KTOT + kc + q * 8;
        const __nv_bfloat16* pal = g_al + (size_t)(m0 + row) * KTOT + kc + q * 8;
        const __nv_bfloat16* pbh = g_wh + (size_t)(n0 + row) * KTOT + kc + q * 8;
        const __nv_bfloat16* pbl = g_wl + (size_t)(n0 + row) * KTOT + kc + q * 8;
        CP_ASYNC16(sb + OFF_AH + soff, pah);
        CP_ASYNC16(sb + OFF_AL + soff, pal);
        CP_ASYNC16(sb + OFF_BH + soff, pbh);
        CP_ASYNC16(sb + OFF_BL + soff, pbl);
    }
}

__global__ __launch_bounds__(256, 1)
void gemm0_mma(const float* __restrict__ bias) {
    extern __shared__ char smem_raw[];
    const uint32_t sbase = (uint32_t)__cvta_generic_to_shared(smem_raw);

    const int tid = threadIdx.x;
    const int wid = tid >> 5;
    const int lane = tid & 31;
    const int m0 = (blockIdx.x >> 1) * 128;
    const int n0 = (blockIdx.x & 1) * 128;
    const int wm = (wid & 1) * 64;
    const int wn = (wid >> 1) * 32;

    float acc[4][4][4];
    #pragma unroll
    for (int a = 0; a < 4; ++a)
        #pragma unroll
        for (int b = 0; b < 4; ++b)
            #pragma unroll
            for (int c = 0; c < 4; ++c) acc[a][b][c] = 0.0f;

    // ldmatrix per-lane base offsets
    const int lrow = lane & 15;           // row within 16-row tile
    const int lcol16 = (lane >> 4) * 16;  // 0 or 16 bytes (k half)

    load_stage(sbase, 0, m0, n0, tid);
    CP_COMMIT();

    for (int c = 0; c < NCHUNK; ++c) {
        if (c + 1 < NCHUNK) {
            load_stage(sbase + (uint32_t)((c + 1) & 1) * STAGE_B, (c + 1) * 64, m0, n0, tid);
        }
        CP_COMMIT();
        CP_WAIT1();
        __syncthreads();

        const uint32_t sA = sbase + (uint32_t)(c & 1) * STAGE_B;
        #pragma unroll
        for (int ks = 0; ks < 4; ++ks) {
            const int colb = ks * 32 + lcol16;

            uint32_t ah[4][4];
            uint32_t al[4][4];
            #pragma unroll
            for (int mf = 0; mf < 4; ++mf) {
                uint32_t off = SWZ128((uint32_t)((wm + mf * 16 + lrow) * 128 + colb));
                LDMATRIX_X4(ah[mf][0], ah[mf][1], ah[mf][2], ah[mf][3], sA + OFF_AH + off);
                LDMATRIX_X4(al[mf][0], al[mf][1], al[mf][2], al[mf][3], sA + OFF_AL + off);
            }

            #pragma unroll
            for (int g = 0; g < 2; ++g) {
                uint32_t bh[4];
                uint32_t bl[4];
                uint32_t off = SWZ128((uint32_t)((wn + g * 16 + lrow) * 128 + colb));
                LDMATRIX_X4(bh[0], bh[1], bh[2], bh[3], sA + OFF_BH + off);
                LDMATRIX_X4(bl[0], bl[1], bl[2], bl[3], sA + OFF_BL + off);
                #pragma unroll
                for (int mf = 0; mf < 4; ++mf) {
                    #pragma unroll
                    for (int blk = 0; blk < 2; ++blk) {
                        float* d = acc[mf][g * 2 + blk];
                        MMA_BF16(d, ah[mf], bh[blk], bh[blk + 2]);
                        MMA_BF16(d, al[mf], bh[blk], bh[blk + 2]);
                        MMA_BF16(d, ah[mf], bl[blk], bl[blk + 2]);
                    }
                }
            }
        }
        __syncthreads();
    }

    // epilogue: bias + relu -> g_h
    #pragma unroll
    for (int mf = 0; mf < 4; ++mf) {
        #pragma unroll
        for (int nf = 0; nf < 4; ++nf) {
            const int r0 = m0 + wm + mf * 16 + (lane >> 2);
            const int cb = n0 + wn + nf * 8 + (lane & 3) * 2;
            const float b0 = __ldg(bias + cb);
            const float b1 = __ldg(bias + cb + 1);
            float2 v0;
            v0.x = fmaxf(acc[mf][nf][0] + b0, 0.0f);
            v0.y = fmaxf(acc[mf][nf][1] + b1, 0.0f);
            float2 v1;
            v1.x = fmaxf(acc[mf][nf][2] + b0, 0.0f);
            v1.y = fmaxf(acc[mf][nf][3] + b1, 0.0f);
            *(float2*)(g_h + (size_t)r0 * HID + cb) = v0;
            *(float2*)(g_h + (size_t)(r0 + 8) * HID + cb) = v1;
        }
    }
}

// ---------------------------------------------------------------------------
// fused layer-1: segment mean over h + output GEMM + log_softmax
// ---------------------------------------------------------------------------
__global__ __launch_bounds__(256)
void out_kernel(const int* __restrict__ src, const int* __restrict__ dst,
                const float* __restrict__ b1, float* __restrict__ out) {
    __shared__ float sA[HID];
    __shared__ float sH[HID];
    __shared__ float logits[OUT_C];

    const int b = blockIdx.x;
    const int tid = threadIdx.x;
    const int start = lower_bound_i(dst, E1_, b);
    const int end   = lower_bound_i(dst, E1_, b + 1);

    float acc = 0.0f;
    for (int e = start; e < end; ++e) {
        acc += g_h[(size_t)src[e] * HID + tid];
    }
    sA[tid] = acc / (float)max(end - start, 1);
    sH[tid] = g_h[(size_t)b * HID + tid];
    __syncthreads();

    const int w = tid >> 5;
    const int l = tid & 31;
    for (int c = w; c < OUT_C; c += 8) {
        const float* wl = g_w1t + (size_t)c * HID;
        const float* wr = g_w1t + (size_t)(OUT_C + c) * HID;
        float s = 0.0f;
        #pragma unroll
        for (int k = l; k < HID; k += 32) {
            s += sA[k] * wl[k] + sH[k] * wr[k];
        }
        #pragma unroll
        for (int o = 16; o; o >>= 1) {
            s += __shfl_xor_sync(0xffffffffu, s, o);
        }
        if (l == 0) logits[c] = s + b1[c];
    }
    __syncthreads();

    if (tid < 32) {
        float v0 = (tid < OUT_C) ? logits[tid] : -3.4e38f;
        float v1 = (tid + 32 < OUT_C) ? logits[tid + 32] : -3.4e38f;
        float m = fmaxf(v0, v1);
        #pragma unroll
        for (int o = 16; o; o >>= 1) {
            m = fmaxf(m, __shfl_xor_sync(0xffffffffu, m, o));
        }
        float es = ((tid < OUT_C) ? expf(v0 - m) : 0.0f) +
                   ((tid + 32 < OUT_C) ? expf(v1 - m) : 0.0f);
        #pragma unroll
        for (int o = 16; o; o >>= 1) {
            es += __shfl_xor_sync(0xffffffffu, es, o);
        }
        float lse = logf(es);
        if (tid < OUT_C) out[(size_t)b * OUT_C + tid] = v0 - m - lse;
        if (tid + 32 < OUT_C) out[(size_t)b * OUT_C + tid + 32] = v1 - m - lse;
    }
}

// ---------------------------------------------------------------------------
extern "C" void kernel_launch(void* const* d_in, const int* in_sizes, int n_in,
                              void* d_out, int out_size) {
    const float* x    = (const float*)d_in[0];
    const float* W_l0 = (const float*)d_in[1];
    const float* b_l0 = (const float*)d_in[2];
    const float* W_r0 = (const float*)d_in[3];
    const float* W_l1 = (const float*)d_in[4];
    const float* b_l1 = (const float*)d_in[5];
    const float* W_r1 = (const float*)d_in[6];
    const int* src0   = (const int*)d_in[7];
    const int* dst0   = (const int*)d_in[8];
    const int* src1   = (const int*)d_in[9];
    const int* dst1   = (const int*)d_in[10];
    float* out = (float*)d_out;

    static int s_attr_done = 0;
    if (!s_attr_done) {
        cudaFuncSetAttribute(gemm0_mma, cudaFuncAttributeMaxDynamicSharedMemorySize,
                             GSM_TOTAL);
        s_attr_done = 1;
    }

    conv_x_kernel<<<(N1_ * KHALF + 255) / 256, 256>>>(x);
    conv_w0_kernel<<<(2 * HID * KHALF + 255) / 256, 256>>>(W_l0, W_r0);
    conv_w1_kernel<<<(2 * OUT_C * HID + 255) / 256, 256>>>(W_l1, W_r1);
    agg0_kernel<<<N1_, 256>>>(x, src0, dst0);
    gemm0_mma<<<160, 256, GSM_TOTAL>>>(b_l0);
    out_kernel<<<B_, 256>>>(src1, dst1, b_l1, out);
}

// round 5
// speedup vs baseline: 1.8313x; 1.2389x over previous
#include <cuda_runtime.h>
#include <cuda_bf16.h>
#include <cstdint>

#define N0_   260000
#define N1_   10240
#define B_    1024
#define E0_   256000
#define E1_   10240
#define IN_C  602
#define HID   256
#define OUT_C 41
#define KHALF 640
#define KTOT  1280
#define NCHUNK 20

// ---------------- scratch ----------------------------------------------------
__device__ __nv_bfloat16 g_ah[(size_t)N1_ * KTOT];
__device__ __nv_bfloat16 g_al[(size_t)N1_ * KTOT];
__device__ __nv_bfloat16 g_wh[(size_t)HID * KTOT];
__device__ __nv_bfloat16 g_wl[(size_t)HID * KTOT];
__device__ float g_h[(size_t)N1_ * HID];
__device__ float g_w1t[2 * OUT_C * HID];

// ---------------- portable PTX macros ---------------------------------------
#define CP_ASYNC16(dst, src) \
    asm volatile("cp.async.cg.shared.global [%0], [%1], 16;" \
        :: "r"((uint32_t)(dst)), "l"(src) : "memory")
#define CP_COMMIT() asm volatile("cp.async.commit_group;" ::: "memory")
#define CP_WAIT1()  asm volatile("cp.async.wait_group 1;" ::: "memory")

#define LDMATRIX_X4(r0, r1, r2, r3, addr) \
    asm volatile("ldmatrix.sync.aligned.m8n8.x4.shared.b16 {%0,%1,%2,%3}, [%4];" \
        : "=r"(r0), "=r"(r1), "=r"(r2), "=r"(r3) : "r"((uint32_t)(addr)))

#define MMA_BF16(d, a, b0_, b1_) \
    asm volatile("mma.sync.aligned.m16n8k16.row.col.f32.bf16.bf16.f32 " \
        "{%0,%1,%2,%3}, {%4,%5,%6,%7}, {%8,%9}, {%0,%1,%2,%3};" \
        : "+f"((d)[0]), "+f"((d)[1]), "+f"((d)[2]), "+f"((d)[3]) \
        : "r"((a)[0]), "r"((a)[1]), "r"((a)[2]), "r"((a)[3]), \
          "r"(b0_), "r"(b1_))

#define SWZ128(o) ((o) ^ (((o) >> 3) & 0x70))

// ---------------------------------------------------------------------------
__device__ __forceinline__ int lower_bound_i(const int* __restrict__ a, int n, int v) {
    int lo = 0;
    int hi = n;
    while (lo < hi) {
        int mid = (lo + hi) >> 1;
        if (a[mid] < v) lo = mid + 1; else hi = mid;
    }
    return lo;
}

__device__ __forceinline__ void store_hl(__nv_bfloat16* H, __nv_bfloat16* L,
                                         size_t idx, float v) {
    __nv_bfloat16 h = __float2bfloat16(v);
    H[idx] = h;
    L[idx] = __float2bfloat16(v - __bfloat162float(h));
}

// ---------------------------------------------------------------------------
// prep: W_l0/W_r0 -> g_wh/g_wl transposed; W_l1/W_r1 -> g_w1t
// ---------------------------------------------------------------------------
#define W0_ELEMS (2 * HID * KHALF)
#define W1_ELEMS (2 * OUT_C * HID)

__global__ void prep_w_kernel(const float* __restrict__ Wl0,
                              const float* __restrict__ Wr0,
                              const float* __restrict__ Wl1,
                              const float* __restrict__ Wr1) {
    int i = blockIdx.x * blockDim.x + threadIdx.x;
    if (i < W0_ELEMS) {
        int m = i / (HID * KHALF);
        int rem = i % (HID * KHALF);
        int n = rem / KHALF;
        int k = rem % KHALF;
        const float* W = m ? Wr0 : Wl0;
        float v = (k < IN_C) ? W[(size_t)k * HID + n] : 0.0f;
        store_hl(g_wh, g_wl, (size_t)n * KTOT + (size_t)m * KHALF + k, v);
    } else {
        int j = i - W0_ELEMS;
        if (j >= W1_ELEMS) return;
        int m = j / (OUT_C * HID);
        int rem = j % (OUT_C * HID);
        int c = rem / HID;
        int k = rem % HID;
        const float* W = m ? Wr1 : Wl1;
        g_w1t[j] = W[(size_t)k * OUT_C + c];
    }
}

// ---------------------------------------------------------------------------
// layer-0 segment mean + x-row conversion, fused. One CTA per target.
// float2 per thread: cols [2t, 2t+1]; threads <45 also cols [512+2t, 513+2t].
// ---------------------------------------------------------------------------
__global__ __launch_bounds__(256)
void agg0x_kernel(const float* __restrict__ x,
                  const int* __restrict__ src,
                  const int* __restrict__ dst) {
    const int t = blockIdx.x;
    const int start = lower_bound_i(dst, E0_, t);
    const int end   = lower_bound_i(dst, E0_, t + 1);
    const int tid = threadIdx.x;
    const int c0 = 2 * tid;
    const int c1 = 512 + 2 * tid;
    const bool has2 = (tid < 45);

    float2 s0 = make_float2(0.0f, 0.0f);
    float2 s1 = make_float2(0.0f, 0.0f);

    int e = start;
    for (; e + 3 < end; e += 4) {
        const int i0 = src[e];
        const int i1 = src[e + 1];
        const int i2 = src[e + 2];
        const int i3 = src[e + 3];
        const float* p0 = x + (size_t)i0 * IN_C;
        const float* p1 = x + (size_t)i1 * IN_C;
        const float* p2 = x + (size_t)i2 * IN_C;
        const float* p3 = x + (size_t)i3 * IN_C;
        float2 a0 = *(const float2*)(p0 + c0);
        float2 a1 = *(const float2*)(p1 + c0);
        float2 a2 = *(const float2*)(p2 + c0);
        float2 a3 = *(const float2*)(p3 + c0);
        if (has2) {
            float2 b0 = *(const float2*)(p0 + c1);
            float2 b1 = *(const float2*)(p1 + c1);
            float2 b2 = *(const float2*)(p2 + c1);
            float2 b3 = *(const float2*)(p3 + c1);
            s1.x += (b0.x + b1.x) + (b2.x + b3.x);
            s1.y += (b0.y + b1.y) + (b2.y + b3.y);
        }
        s0.x += (a0.x + a1.x) + (a2.x + a3.x);
        s0.y += (a0.y + a1.y) + (a2.y + a3.y);
    }
    for (; e < end; ++e) {
        const float* p0 = x + (size_t)src[e] * IN_C;
        float2 a0 = *(const float2*)(p0 + c0);
        s0.x += a0.x;
        s0.y += a0.y;
        if (has2) {
            float2 b0 = *(const float2*)(p0 + c1);
            s1.x += b0.x;
            s1.y += b0.y;
        }
    }

    const float inv = 1.0f / (float)max(end - start, 1);
    const size_t base = (size_t)t * KTOT;
    store_hl(g_ah, g_al, base + c0, s0.x * inv);
    store_hl(g_ah, g_al, base + c0 + 1, s0.y * inv);
    if (has2) {
        store_hl(g_ah, g_al, base + c1, s1.x * inv);
        store_hl(g_ah, g_al, base + c1 + 1, s1.y * inv);
    } else if (tid < 64) {
        store_hl(g_ah, g_al, base + c1, 0.0f);     // pad cols 602..639
        store_hl(g_ah, g_al, base + c1 + 1, 0.0f);
    }

    // fused conv_x: row t -> cols 640..1279
    const float* xr = x + (size_t)t * IN_C;
    float2 v0 = *(const float2*)(xr + c0);
    store_hl(g_ah, g_al, base + KHALF + c0, v0.x);
    store_hl(g_ah, g_al, base + KHALF + c0 + 1, v0.y);
    if (has2) {
        float2 v1 = *(const float2*)(xr + c1);
        store_hl(g_ah, g_al, base + KHALF + c1, v1.x);
        store_hl(g_ah, g_al, base + KHALF + c1 + 1, v1.y);
    } else if (tid < 64) {
        store_hl(g_ah, g_al, base + KHALF + c1, 0.0f);
        store_hl(g_ah, g_al, base + KHALF + c1 + 1, 0.0f);
    }
}

// ---------------------------------------------------------------------------
// layer-0 GEMM: tile M=160, N=128, grid 64x2=128 CTAs (single clean wave).
// warp tile 80x32 (8 warps: 2M x 4N), K chunks of 64, cp.async 2-stage.
// ---------------------------------------------------------------------------
#define TM       160
#define OFF_AH   0u
#define OFF_AL   20480u
#define OFF_BH   40960u
#define OFF_BL   57344u
#define STAGE_B  73728u
#define GSM_TOTAL (2 * 73728)

__device__ __forceinline__ void load_stage(uint32_t sb, int kc, int m0, int n0, int tid) {
    #pragma unroll
    for (int j = 0; j < 18; ++j) {
        int i = tid + 256 * j;
        if (j < 5) {
            int row = i >> 3;
            int q = i & 7;
            uint32_t d = OFF_AH + SWZ128((uint32_t)(row * 128 + q * 16));
            CP_ASYNC16(sb + d, g_ah + (size_t)(m0 + row) * KTOT + kc + q * 8);
        } else if (j < 10) {
            int ii = i - 1280;
            int row = ii >> 3;
            int q = ii & 7;
            uint32_t d = OFF_AL + SWZ128((uint32_t)(row * 128 + q * 16));
            CP_ASYNC16(sb + d, g_al + (size_t)(m0 + row) * KTOT + kc + q * 8);
        } else if (j < 14) {
            int ii = i - 2560;
            int row = ii >> 3;
            int q = ii & 7;
            uint32_t d = OFF_BH + SWZ128((uint32_t)(row * 128 + q * 16));
            CP_ASYNC16(sb + d, g_wh + (size_t)(n0 + row) * KTOT + kc + q * 8);
        } else {
            int ii = i - 3584;
            int row = ii >> 3;
            int q = ii & 7;
            uint32_t d = OFF_BL + SWZ128((uint32_t)(row * 128 + q * 16));
            CP_ASYNC16(sb + d, g_wl + (size_t)(n0 + row) * KTOT + kc + q * 8);
        }
    }
}

__global__ __launch_bounds__(256, 1)
void gemm0_mma(const float* __restrict__ bias) {
    extern __shared__ char smem_raw[];
    const uint32_t sbase = (uint32_t)__cvta_generic_to_shared(smem_raw);

    const int tid = threadIdx.x;
    const int wid = tid >> 5;
    const int lane = tid & 31;
    const int m0 = (blockIdx.x >> 1) * TM;
    const int n0 = (blockIdx.x & 1) * 128;
    const int wm = (wid & 1) * 80;
    const int wn = (wid >> 1) * 32;

    float acc[5][4][4];
    #pragma unroll
    for (int a = 0; a < 5; ++a)
        #pragma unroll
        for (int b = 0; b < 4; ++b)
            #pragma unroll
            for (int c = 0; c < 4; ++c) acc[a][b][c] = 0.0f;

    const int lrow = lane & 15;
    const int lcol16 = (lane >> 4) * 16;

    load_stage(sbase, 0, m0, n0, tid);
    CP_COMMIT();

    for (int c = 0; c < NCHUNK; ++c) {
        if (c + 1 < NCHUNK) {
            load_stage(sbase + (uint32_t)((c + 1) & 1) * STAGE_B, (c + 1) * 64, m0, n0, tid);
        }
        CP_COMMIT();
        CP_WAIT1();
        __syncthreads();

        const uint32_t sA = sbase + (uint32_t)(c & 1) * STAGE_B;
        #pragma unroll
        for (int ks = 0; ks < 4; ++ks) {
            const int colb = ks * 32 + lcol16;

            uint32_t bh[2][4];
            uint32_t bl[2][4];
            #pragma unroll
            for (int g = 0; g < 2; ++g) {
                uint32_t off = SWZ128((uint32_t)((wn + g * 16 + lrow) * 128 + colb));
                LDMATRIX_X4(bh[g][0], bh[g][1], bh[g][2], bh[g][3], sA + OFF_BH + off);
                LDMATRIX_X4(bl[g][0], bl[g][1], bl[g][2], bl[g][3], sA + OFF_BL + off);
            }

            #pragma unroll
            for (int mf = 0; mf < 5; ++mf) {
                uint32_t ah[4];
                uint32_t al[4];
                uint32_t off = SWZ128((uint32_t)((wm + mf * 16 + lrow) * 128 + colb));
                LDMATRIX_X4(ah[0], ah[1], ah[2], ah[3], sA + OFF_AH + off);
                LDMATRIX_X4(al[0], al[1], al[2], al[3], sA + OFF_AL + off);
                #pragma unroll
                for (int g = 0; g < 2; ++g) {
                    #pragma unroll
                    for (int blk = 0; blk < 2; ++blk) {
                        float* d = acc[mf][g * 2 + blk];
                        MMA_BF16(d, ah, bh[g][blk], bh[g][blk + 2]);
                        MMA_BF16(d, al, bh[g][blk], bh[g][blk + 2]);
                        MMA_BF16(d, ah, bl[g][blk], bl[g][blk + 2]);
                    }
                }
            }
        }
        __syncthreads();
    }

    #pragma unroll
    for (int mf = 0; mf < 5; ++mf) {
        #pragma unroll
        for (int nf = 0; nf < 4; ++nf) {
            const int r0 = m0 + wm + mf * 16 + (lane >> 2);
            const int cb = n0 + wn + nf * 8 + (lane & 3) * 2;
            const float b0 = __ldg(bias + cb);
            const float b1 = __ldg(bias + cb + 1);
            float2 v0;
            v0.x = fmaxf(acc[mf][nf][0] + b0, 0.0f);
            v0.y = fmaxf(acc[mf][nf][1] + b1, 0.0f);
            float2 v1;
            v1.x = fmaxf(acc[mf][nf][2] + b0, 0.0f);
            v1.y = fmaxf(acc[mf][nf][3] + b1, 0.0f);
            *(float2*)(g_h + (size_t)r0 * HID + cb) = v0;
            *(float2*)(g_h + (size_t)(r0 + 8) * HID + cb) = v1;
        }
    }
}

// ---------------------------------------------------------------------------
// fused layer-1: segment mean over h + output GEMM + log_softmax
// ---------------------------------------------------------------------------
__global__ __launch_bounds__(256)
void out_kernel(const int* __restrict__ src, const int* __restrict__ dst,
                const float* __restrict__ b1, float* __restrict__ out) {
    __shared__ float sA[HID];
    __shared__ float sH[HID];
    __shared__ float logits[OUT_C];

    const int b = blockIdx.x;
    const int tid = threadIdx.x;
    const int start = lower_bound_i(dst, E1_, b);
    const int end   = lower_bound_i(dst, E1_, b + 1);

    float acc = 0.0f;
    for (int e = start; e < end; ++e) {
        acc += g_h[(size_t)src[e] * HID + tid];
    }
    sA[tid] = acc / (float)max(end - start, 1);
    sH[tid] = g_h[(size_t)b * HID + tid];
    __syncthreads();

    const int w = tid >> 5;
    const int l = tid & 31;
    for (int c = w; c < OUT_C; c += 8) {
        const float* wl = g_w1t + (size_t)c * HID;
        const float* wr = g_w1t + (size_t)(OUT_C + c) * HID;
        float s = 0.0f;
        #pragma unroll
        for (int k = l; k < HID; k += 32) {
            s += sA[k] * wl[k] + sH[k] * wr[k];
        }
        #pragma unroll
        for (int o = 16; o; o >>= 1) {
            s += __shfl_xor_sync(0xffffffffu, s, o);
        }
        if (l == 0) logits[c] = s + b1[c];
    }
    __syncthreads();

    if (tid < 32) {
        float v0 = (tid < OUT_C) ? logits[tid] : -3.4e38f;
        float v1 = (tid + 32 < OUT_C) ? logits[tid + 32] : -3.4e38f;
        float m = fmaxf(v0, v1);
        #pragma unroll
        for (int o = 16; o; o >>= 1) {
            m = fmaxf(m, __shfl_xor_sync(0xffffffffu, m, o));
        }
        float es = ((tid < OUT_C) ? expf(v0 - m) : 0.0f) +
                   ((tid + 32 < OUT_C) ? expf(v1 - m) : 0.0f);
        #pragma unroll
        for (int o = 16; o; o >>= 1) {
            es += __shfl_xor_sync(0xffffffffu, es, o);
        }
        float lse = logf(es);
        if (tid < OUT_C) out[(size_t)b * OUT_C + tid] = v0 - m - lse;
        if (tid + 32 < OUT_C) out[(size_t)b * OUT_C + tid + 32] = v1 - m - lse;
    }
}

// ---------------------------------------------------------------------------
extern "C" void kernel_launch(void* const* d_in, const int* in_sizes, int n_in,
                              void* d_out, int out_size) {
    const float* x    = (const float*)d_in[0];
    const float* W_l0 = (const float*)d_in[1];
    const float* b_l0 = (const float*)d_in[2];
    const float* W_r0 = (const float*)d_in[3];
    const float* W_l1 = (const float*)d_in[4];
    const float* b_l1 = (const float*)d_in[5];
    const float* W_r1 = (const float*)d_in[6];
    const int* src0   = (const int*)d_in[7];
    const int* dst0   = (const int*)d_in[8];
    const int* src1   = (const int*)d_in[9];
    const int* dst1   = (const int*)d_in[10];
    float* out = (float*)d_out;

    static int s_attr_done = 0;
    if (!s_attr_done) {
        cudaFuncSetAttribute(gemm0_mma, cudaFuncAttributeMaxDynamicSharedMemorySize,
                             GSM_TOTAL);
        s_attr_done = 1;
    }

    prep_w_kernel<<<(W0_ELEMS + W1_ELEMS + 255) / 256, 256>>>(W_l0, W_r0, W_l1, W_r1);
    agg0x_kernel<<<N1_, 256>>>(x, src0, dst0);
    gemm0_mma<<<128, 256, GSM_TOTAL>>>(b_l0);
    out_kernel<<<B_, 256>>>(src1, dst1, b_l1, out);
}